// round 7
// baseline (speedup 1.0000x reference)
#include <cuda_runtime.h>
#include <cuda_bf16.h>
#include <cstdint>

#define B_    4
#define T_    4096
#define D_    1024
#define H_    16
#define DH_   64
#define NS_   4
#define CTX_  516
#define Q0_   3580
#define MTOT_ (B_*CTX_)   // 2064
#define XR_   520         // per-batch gathered x rows: 4 sinks + 516 window

// ---------------------------------------------------------------------------
// Device scratch (no allocation allowed)
// ---------------------------------------------------------------------------
__device__ __align__(16) __nv_bfloat16 g_Xh[B_*XR_*D_];
__device__ __align__(16) __nv_bfloat16 g_Xl[B_*XR_*D_];
__device__ __align__(16) __nv_bfloat16 g_Wth[4*D_*D_];   // W^T hi: [z][n][k]
__device__ __align__(16) __nv_bfloat16 g_Wtl[4*D_*D_];   // W^T lo
__device__ __align__(16) float g_Q[MTOT_*D_];
__device__ __align__(16) float g_K[MTOT_*D_];
__device__ __align__(16) float g_V[MTOT_*D_];
__device__ __align__(16) __nv_bfloat16 g_AOh[MTOT_*D_];
__device__ __align__(16) __nv_bfloat16 g_AOl[MTOT_*D_];

// ---------------------------------------------------------------------------
__device__ __forceinline__ uint32_t smem_u32(const void* p) {
    uint32_t a;
    asm("{ .reg .u64 t; cvta.to.shared.u64 t, %1; cvt.u32.u64 %0, t; }" : "=r"(a) : "l"(p));
    return a;
}
__device__ __forceinline__ uint32_t pack_bf2(float a, float b) {
    return ((uint32_t)__bfloat16_as_ushort(__float2bfloat16_rn(b)) << 16) |
           (uint32_t)__bfloat16_as_ushort(__float2bfloat16_rn(a));
}
__device__ __forceinline__ void ldsm4(uint32_t* r, uint32_t addr) {
    asm volatile("ldmatrix.sync.aligned.m8n8.x4.shared.b16 {%0,%1,%2,%3}, [%4];"
        : "=r"(r[0]), "=r"(r[1]), "=r"(r[2]), "=r"(r[3]) : "r"(addr));
}
__device__ __forceinline__ void ldsm2(uint32_t* r, uint32_t addr) {
    asm volatile("ldmatrix.sync.aligned.m8n8.x2.shared.b16 {%0,%1}, [%2];"
        : "=r"(r[0]), "=r"(r[1]) : "r"(addr));
}
__device__ __forceinline__ void mma16816(float* c, const uint32_t* a, const uint32_t* b) {
    asm volatile(
        "mma.sync.aligned.m16n8k16.row.col.f32.bf16.bf16.f32 "
        "{%0,%1,%2,%3}, {%4,%5,%6,%7}, {%8,%9}, {%0,%1,%2,%3};"
        : "+f"(c[0]), "+f"(c[1]), "+f"(c[2]), "+f"(c[3])
        : "r"(a[0]), "r"(a[1]), "r"(a[2]), "r"(a[3]), "r"(b[0]), "r"(b[1]));
}
__device__ __forceinline__ void cpa16(uint32_t dst, const void* src, bool valid) {
    int sz = valid ? 16 : 0;
    asm volatile("cp.async.cg.shared.global [%0], [%1], 16, %2;"
        :: "r"(dst), "l"(src), "r"(sz) : "memory");
}
#define CPA_COMMIT() asm volatile("cp.async.commit_group;" ::: "memory")
#define CPA_WAIT(n)  asm volatile("cp.async.wait_group %0;" :: "n"(n) : "memory")

// packed fp32x2 (Blackwell family-wide; plain sm_100)
__device__ __forceinline__ unsigned long long pk2(float a, float b) {
    unsigned long long r;
    asm("mov.b64 %0, {%1, %2};" : "=l"(r) : "f"(a), "f"(b));
    return r;
}
__device__ __forceinline__ void upk2(float& a, float& b, unsigned long long v) {
    asm("mov.b64 {%0, %1}, %2;" : "=f"(a), "=f"(b) : "l"(v));
}
#define FMA2(d, a, b, c) asm("fma.rn.f32x2 %0, %1, %2, %3;" : "=l"(d) : "l"(a), "l"(b), "l"(c))

// ---------------------------------------------------------------------------
// Zero-fill the structurally-zero output rows
// ---------------------------------------------------------------------------
__global__ void zero_kernel(float* __restrict__ out) {
    size_t idx = (size_t)blockIdx.x * blockDim.x + threadIdx.x;
    const size_t n4 = (size_t)B_ * Q0_ * D_ / 4;
    if (idx < n4) {
        size_t e = idx * 4;
        const size_t perb = (size_t)Q0_ * D_;
        size_t b = e / perb, r = e % perb;
        *(float4*)(out + b * (size_t)T_ * D_ + r) = make_float4(0.f, 0.f, 0.f, 0.f);
    }
}

// ---------------------------------------------------------------------------
// prep_x: gather live x rows, split fp32 -> bf16 hi/lo
// ---------------------------------------------------------------------------
__global__ __launch_bounds__(256) void prep_x(const float* __restrict__ x) {
    int gr = blockIdx.x;            // 0..2079
    int b = gr / XR_, r = gr % XR_;
    int tok = (r < NS_) ? r : (Q0_ + (r - NS_));
    int t = threadIdx.x;
    float4 v = *(const float4*)(x + (size_t)(b * T_ + tok) * D_ + t * 4);
    float h0 = __bfloat162float(__float2bfloat16_rn(v.x));
    float h1 = __bfloat162float(__float2bfloat16_rn(v.y));
    float h2 = __bfloat162float(__float2bfloat16_rn(v.z));
    float h3 = __bfloat162float(__float2bfloat16_rn(v.w));
    uint2 hw = make_uint2(pack_bf2(v.x, v.y), pack_bf2(v.z, v.w));
    uint2 lw = make_uint2(pack_bf2(v.x - h0, v.y - h1), pack_bf2(v.z - h2, v.w - h3));
    ((uint2*)g_Xh)[(size_t)gr * 256 + t] = hw;
    ((uint2*)g_Xl)[(size_t)gr * 256 + t] = lw;
}

// ---------------------------------------------------------------------------
// prep_w: transpose W (4 matrices) -> [n][k] bf16 hi/lo
// ---------------------------------------------------------------------------
__global__ __launch_bounds__(256) void prep_w(
    const float* __restrict__ Wq, const float* __restrict__ Wk,
    const float* __restrict__ Wv, const float* __restrict__ Wo)
{
    const int z = blockIdx.z;
    const float* __restrict__ W = (z == 0) ? Wq : (z == 1) ? Wk : (z == 2) ? Wv : Wo;
    __shared__ float tile[64][33];
    const int n0 = blockIdx.x * 32, k0 = blockIdx.y * 64;
    const int tx = threadIdx.x, ty = threadIdx.y;

    #pragma unroll
    for (int rr = 0; rr < 8; rr++) {
        int kk = ty + rr * 8;
        tile[kk][tx] = W[(size_t)(k0 + kk) * D_ + n0 + tx];
    }
    __syncthreads();
    #pragma unroll
    for (int rr = 0; rr < 4; rr++) {
        int n = ty + rr * 8;
        float v0 = tile[tx * 2][n], v1 = tile[tx * 2 + 1][n];
        float h0 = __bfloat162float(__float2bfloat16_rn(v0));
        float h1 = __bfloat162float(__float2bfloat16_rn(v1));
        size_t base = (size_t)z * D_ * D_ + (size_t)(n0 + n) * D_ + k0;
        ((uint32_t*)(g_Wth + base))[tx] = pack_bf2(v0, v1);
        ((uint32_t*)(g_Wtl + base))[tx] = pack_bf2(v0 - h0, v1 - h1);
    }
}

// ---------------------------------------------------------------------------
// Tensor-core GEMM via mma.sync + cp.async 2-stage pipeline.
// C[128x128] = A(hi/lo) x B(hi/lo)^T, K=1024, 3-term hi/lo split.
// 8 warps 2x4; warp tile 64x32; K-chunk 32. __launch_bounds__(256,2).
// ---------------------------------------------------------------------------
#define GM 128
#define GN 128
#define KC 32
#define SPAD 40
#define NCHUNK (D_/KC)                // 32
#define STG  (GM*SPAD)                // halves per stage per array
#define STGB (STG*2)                  // bytes per stage per array
#define GSMEM (8*STG*2)               // 4 arrays x 2 stages = 81920 bytes

__global__ __launch_bounds__(256, 2) void gemm_mma(int mode_base, float* __restrict__ outF) {
    extern __shared__ __nv_bfloat16 ds[];
    __nv_bfloat16* sAh = ds;
    __nv_bfloat16* sAl = ds + 2 * STG;
    __nv_bfloat16* sBh = ds + 4 * STG;
    __nv_bfloat16* sBl = ds + 6 * STG;

    const int mode = mode_base + blockIdx.z;
    const int n0 = blockIdx.x * GN;
    const int m0 = blockIdx.y * GM;
    const int tid = threadIdx.x;
    const int wid = tid >> 5, lane = tid & 31;
    const int warp_m = (wid & 1) * 64;
    const int warp_n = (wid >> 1) * 32;

    const __nv_bfloat16* __restrict__ Bh_g = g_Wth + (size_t)mode * D_ * D_;
    const __nv_bfloat16* __restrict__ Bl_g = g_Wtl + (size_t)mode * D_ * D_;
    const __nv_bfloat16* __restrict__ Ah_g = (mode < 3) ? g_Xh : g_AOh;
    const __nv_bfloat16* __restrict__ Al_g = (mode < 3) ? g_Xl : g_AOl;

    // Loader geometry: rows ar0 and ar0+64, 16B quad q.
    const int ar0 = tid >> 2, ar1 = ar0 + 64;
    const int q = tid & 3;
    long asrc0 = -1, asrc1 = -1;
    {
        int m = m0 + ar0;
        if (m < MTOT_) {
            if (mode < 3) { int b = m / CTX_, i = m % CTX_; asrc0 = (long)b * XR_ + ((mode == 0) ? (NS_ + i) : ((i < NS_) ? i : (NS_ + i))); }
            else asrc0 = m;
        }
        m = m0 + ar1;
        if (m < MTOT_) {
            if (mode < 3) { int b = m / CTX_, i = m % CTX_; asrc1 = (long)b * XR_ + ((mode == 0) ? (NS_ + i) : ((i < NS_) ? i : (NS_ + i))); }
            else asrc1 = m;
        }
    }
    const int so0 = ar0 * SPAD + q * 8;
    const int so1 = ar1 * SPAD + q * 8;
    const uint32_t dAh0 = smem_u32(sAh + so0), dAh1 = smem_u32(sAh + so1);
    const uint32_t dAl0 = smem_u32(sAl + so0), dAl1 = smem_u32(sAl + so1);
    const uint32_t dBh0 = smem_u32(sBh + so0), dBh1 = smem_u32(sBh + so1);
    const uint32_t dBl0 = smem_u32(sBl + so0), dBl1 = smem_u32(sBl + so1);

    // Fragment read addresses (stage 0)
    const int a_row = (lane & 15), a_kh = (lane >> 4) << 3;
    const int b_row = (lane & 7),  b_kh = ((lane >> 3) & 1) << 3;
    uint32_t aAh[4], aAl[4], aBh[4], aBl[4];
    #pragma unroll
    for (int mt = 0; mt < 4; mt++) {
        int r = warp_m + mt * 16 + a_row;
        aAh[mt] = smem_u32(sAh + r * SPAD + a_kh);
        aAl[mt] = smem_u32(sAl + r * SPAD + a_kh);
    }
    #pragma unroll
    for (int nt = 0; nt < 4; nt++) {
        int r = warp_n + nt * 8 + b_row;
        aBh[nt] = smem_u32(sBh + r * SPAD + b_kh);
        aBl[nt] = smem_u32(sBl + r * SPAD + b_kh);
    }

    float acc[4][4][4];
    #pragma unroll
    for (int a = 0; a < 4; a++)
        #pragma unroll
        for (int b = 0; b < 4; b++)
            #pragma unroll
            for (int cc = 0; cc < 4; cc++) acc[a][b][cc] = 0.f;

    auto issue = [&](int c) {
        const uint32_t so = (uint32_t)(c & 1) * STGB;
        const size_t koff = (size_t)c * KC + q * 8;
        const size_t a0 = (asrc0 >= 0 ? (size_t)asrc0 : 0) * D_ + koff;
        const size_t a1 = (asrc1 >= 0 ? (size_t)asrc1 : 0) * D_ + koff;
        cpa16(dAh0 + so, Ah_g + a0, asrc0 >= 0);
        cpa16(dAh1 + so, Ah_g + a1, asrc1 >= 0);
        cpa16(dAl0 + so, Al_g + a0, asrc0 >= 0);
        cpa16(dAl1 + so, Al_g + a1, asrc1 >= 0);
        cpa16(dBh0 + so, Bh_g + (size_t)(n0 + ar0) * D_ + koff, true);
        cpa16(dBh1 + so, Bh_g + (size_t)(n0 + ar1) * D_ + koff, true);
        cpa16(dBl0 + so, Bl_g + (size_t)(n0 + ar0) * D_ + koff, true);
        cpa16(dBl1 + so, Bl_g + (size_t)(n0 + ar1) * D_ + koff, true);
        CPA_COMMIT();
    };

    issue(0);
    issue(1);
    for (int c = 0; c < NCHUNK; c++) {
        if (c == NCHUNK - 1) { CPA_WAIT(0); } else { CPA_WAIT(1); }
        __syncthreads();
        const uint32_t so = (uint32_t)(c & 1) * STGB;
        #pragma unroll
        for (int ks = 0; ks < KC * 2; ks += 32) {   // bytes (16 halves)
            uint32_t fBh[4][2], fBl[4][2];
            #pragma unroll
            for (int nt = 0; nt < 4; nt++) {
                ldsm2(fBh[nt], aBh[nt] + so + ks);
                ldsm2(fBl[nt], aBl[nt] + so + ks);
            }
            #pragma unroll
            for (int mt = 0; mt < 4; mt++) {
                uint32_t fA[4];
                ldsm4(fA, aAh[mt] + so + ks);
                #pragma unroll
                for (int nt = 0; nt < 4; nt++) mma16816(acc[mt][nt], fA, fBh[nt]);
                #pragma unroll
                for (int nt = 0; nt < 4; nt++) mma16816(acc[mt][nt], fA, fBl[nt]);
                ldsm4(fA, aAl[mt] + so + ks);
                #pragma unroll
                for (int nt = 0; nt < 4; nt++) mma16816(acc[mt][nt], fA, fBh[nt]);
            }
        }
        __syncthreads();
        if (c + 2 < NCHUNK) issue(c + 2);
    }

    // Epilogue
    const int er = lane >> 2, ec = (lane & 3) * 2;
    #pragma unroll
    for (int mt = 0; mt < 4; mt++) {
        #pragma unroll
        for (int half = 0; half < 2; half++) {
            int mm = m0 + warp_m + mt * 16 + er + half * 8;
            if (mm < MTOT_) {
                float* dst;
                if (mode < 3) {
                    float* outp = (mode == 0) ? g_Q : (mode == 1) ? g_K : g_V;
                    dst = outp + (size_t)mm * D_ + n0;
                } else {
                    int b = mm / CTX_, i = mm % CTX_;
                    dst = outF + (size_t)(b * T_ + Q0_ + i) * D_ + n0;
                }
                #pragma unroll
                for (int nt = 0; nt < 4; nt++) {
                    float2 v = make_float2(acc[mt][nt][half * 2], acc[mt][nt][half * 2 + 1]);
                    *(float2*)(dst + warp_n + nt * 8 + ec) = v;
                }
            }
        }
    }
}

// ---------------------------------------------------------------------------
// Attention: one thread per query, lazy-rescale online softmax, packed f32x2.
// Emits AO as bf16 hi/lo for the tensor-core output projection.
// ---------------------------------------------------------------------------
#define BQ 128
#define KT 64

__global__ __launch_bounds__(BQ) void attn_kernel() {
    const int b = blockIdx.z, h = blockIdx.y, qt = blockIdx.x;
    const int qi = qt * BQ + threadIdx.x;
    const bool act = qi < CTX_;

    unsigned long long q2[DH_ / 2];
    #pragma unroll
    for (int d = 0; d < DH_ / 2; d++) q2[d] = 0ULL;
    if (act) {
        const unsigned long long* qp = (const unsigned long long*)
            (g_Q + (size_t)(b * CTX_ + qi) * D_ + h * DH_);
        #pragma unroll
        for (int d = 0; d < DH_ / 2; d++) q2[d] = qp[d];
    }

    unsigned long long a2[DH_ / 2];
    #pragma unroll
    for (int d = 0; d < DH_ / 2; d++) a2[d] = 0ULL;
    float mval = -1e30f, lsum = 0.f;

    __shared__ float Ks[KT][DH_];
    __shared__ float Vs[KT][DH_];

    const int jmax = min(CTX_ - 1, qt * BQ + BQ - 1);
    for (int j0 = 0; j0 <= jmax; j0 += KT) {
        for (int it = threadIdx.x; it < KT * DH_ / 4; it += BQ) {
            int jj = it >> 4;
            int dd = (it & 15) * 4;
            int j = j0 + jj;
            float4 kv = make_float4(0.f, 0.f, 0.f, 0.f);
            float4 vv = make_float4(0.f, 0.f, 0.f, 0.f);
            if (j < CTX_) {
                size_t off = (size_t)(b * CTX_ + j) * D_ + h * DH_ + dd;
                kv = *(const float4*)(g_K + off);
                vv = *(const float4*)(g_V + off);
            }
            *(float4*)&Ks[jj][dd] = kv;
            *(float4*)&Vs[jj][dd] = vv;
        }
        __syncthreads();

        int jend = act ? min(KT, qi - j0 + 1) : 0;
        for (int jj = 0; jj < jend; jj++) {
            const unsigned long long* k2 = (const unsigned long long*)&Ks[jj][0];
            unsigned long long s2a = 0ULL, s2b = 0ULL;
            #pragma unroll
            for (int d = 0; d < DH_ / 2; d += 2) {
                FMA2(s2a, q2[d],     k2[d],     s2a);
                FMA2(s2b, q2[d + 1], k2[d + 1], s2b);
            }
            float x0, x1, y0, y1;
            upk2(x0, x1, s2a);
            upk2(y0, y1, s2b);
            float s = ((x0 + y0) + (x1 + y1)) * 0.125f;

            const unsigned long long* v2 = (const unsigned long long*)&Vs[jj][0];
            if (s <= mval) {
                float p = __expf(s - mval);
                lsum += p;
                unsigned long long p2 = pk2(p, p);
                #pragma unroll
                for (int d = 0; d < DH_ / 2; d++)
                    FMA2(a2[d], p2, v2[d], a2[d]);          // a += p*v
            } else {
                float cc = __expf(mval - s);
                mval = s;
                lsum = lsum * cc + 1.f;
                unsigned long long c2 = pk2(cc, cc);
                #pragma unroll
                for (int d = 0; d < DH_ / 2; d++)
                    FMA2(a2[d], a2[d], c2, v2[d]);          // a = a*c + v
            }
        }
        __syncthreads();
    }

    if (act) {
        float inv = 1.f / lsum;
        size_t base = (size_t)(b * CTX_ + qi) * D_ + h * DH_;
        #pragma unroll
        for (int d = 0; d < DH_ / 2; d++) {
            float o0, o1;
            upk2(o0, o1, a2[d]);
            o0 *= inv; o1 *= inv;
            float h0 = __bfloat162float(__float2bfloat16_rn(o0));
            float h1 = __bfloat162float(__float2bfloat16_rn(o1));
            *(uint32_t*)(g_AOh + base + d * 2) = pack_bf2(o0, o1);
            *(uint32_t*)(g_AOl + base + d * 2) = pack_bf2(o0 - h0, o1 - h1);
        }
    }
}

// ---------------------------------------------------------------------------
extern "C" void kernel_launch(void* const* d_in, const int* in_sizes, int n_in,
                              void* d_out, int out_size) {
    const float* x  = (const float*)d_in[0];
    const float* Wq = (const float*)d_in[1];
    const float* Wk = (const float*)d_in[2];
    const float* Wv = (const float*)d_in[3];
    const float* Wo = (const float*)d_in[4];
    float* out = (float*)d_out;

    cudaFuncSetAttribute(gemm_mma, cudaFuncAttributeMaxDynamicSharedMemorySize, GSMEM);

    // 1. Zero structurally-zero output rows
    {
        size_t n4 = (size_t)B_ * Q0_ * D_ / 4;
        zero_kernel<<<(int)((n4 + 255) / 256), 256>>>(out);
    }
    // 2. Prep: gather+split x rows; transpose+split weights
    prep_x<<<B_ * XR_, 256>>>(x);
    prep_w<<<dim3(D_ / 32, D_ / 64, 4), dim3(32, 8)>>>(Wq, Wk, Wv, Wo);

    // 3. Q/K/V projections on tensor cores (modes 0,1,2)
    gemm_mma<<<dim3(D_ / GN, (MTOT_ + GM - 1) / GM, 3), 256, GSMEM>>>(0, nullptr);

    // 4. Attention
    attn_kernel<<<dim3((CTX_ + BQ - 1) / BQ, H_, B_), BQ>>>();

    // 5. Output projection (mode 3), scattered to live rows
    gemm_mma<<<dim3(D_ / GN, (MTOT_ + GM - 1) / GM, 1), 256, GSMEM>>>(3, out);
}